// round 8
// baseline (speedup 1.0000x reference)
#include <cuda_runtime.h>
#include <cstdint>

#define MARGIN 0.3f
#define EPSV   1e-6f

#define MAX_B 8192
#define MAX_L 1024
#define UINF  0xFFFFFFFFu

// One memset-able init region: packed (min1<<32 | min2) per label, then diff.
struct OccTab {
    unsigned long long tab[MAX_L];
    unsigned int diff;      // first index with label != label[0]
};
__device__ OccTab g_occ;
__device__ int    g_lab32[MAX_B];   // decoded int32 labels
__device__ float  g_loss[MAX_B];    // per-anchor loss; -1.0f = invalid

// ================================================================ kernel A
// Multi-block occurrence pass: packed 2-min CAS per label (global, spread).
__global__ void k_occ(const void* __restrict__ labels, int B) {
    int t = threadIdx.x;
    int gtid = blockIdx.x * blockDim.x + t;
    int lane = t & 31;
    __shared__ unsigned s_diff;
    if (t == 0) s_diff = UINF;

    // dtype detect, block-local + redundant (no cross-block sync needed).
    // Odd 32-bit words < B are high halves of int64 labels (zero when
    // labels < 2^32) or independent int32 labels (never all zero).
    const int* w = (const int*)labels;
    int any = 0;
    for (int i = 2 * t + 1; i < B; i += 2 * blockDim.x) any |= w[i];
    int is64 = (__syncthreads_or(any) == 0);

    int l0 = is64 ? (int)((const long long*)labels)[0] : w[0];

    unsigned cand = UINF;
    if (gtid < B) {
        int lab = is64 ? (int)((const long long*)labels)[gtid] : w[gtid];
        g_lab32[gtid] = lab;

        if ((unsigned)lab < MAX_L) {
            unsigned long long* addr = &g_occ.tab[lab];
            unsigned long long old = __ldcg(addr);   // L2 read (atomics live in L2)
            unsigned idx = (unsigned)gtid;
            while (true) {
                unsigned m1 = (unsigned)(old >> 32);
                unsigned m2 = (unsigned)old;
                unsigned long long nw;
                if (idx < m1)                      nw = ((unsigned long long)idx << 32) | m1;
                else if (idx != m1 && idx < m2)    nw = ((unsigned long long)m1 << 32) | idx;
                else break;                        // no change needed
                unsigned long long prev = atomicCAS(addr, old, nw);
                if (prev == old) break;
                old = prev;
            }
        }
        if (lab != l0) cand = (unsigned)gtid;
    }

    // g_diff: warp reduce -> smem -> one global atomic per block
    #pragma unroll
    for (int off = 16; off > 0; off >>= 1)
        cand = min(cand, __shfl_down_sync(0xffffffffu, cand, off));
    if (lane == 0 && cand != UINF) atomicMin(&s_diff, cand);
    __syncthreads();
    if (t == 0 && s_diff != UINF) atomicMin(&g_occ.diff, s_diff);
}

// ================================================================ kernel B
// Warp per anchor: resolve pos/neg from packed table, then distances.
__global__ void k_dist(const float* __restrict__ features, int B, int D) {
    int warp = (blockIdx.x * blockDim.x + threadIdx.x) >> 5;
    int lane = threadIdx.x & 31;
    if (warp >= B) return;

    int lab = g_lab32[warp];
    unsigned p = UINF, n = UINF;
    if ((unsigned)lab < MAX_L) {
        unsigned long long packed = __ldcg(&g_occ.tab[lab]);
        unsigned m1 = (unsigned)(packed >> 32);
        unsigned m2 = (unsigned)packed;
        p = (m1 == (unsigned)warp) ? m2 : m1;
        n = (lab != g_lab32[0]) ? 0u : __ldcg(&g_occ.diff);
    }
    if (p == UINF || n == UINF) {
        if (lane == 0) g_loss[warp] = -1.0f;
        return;
    }

    const float4* __restrict__ A = (const float4*)(features + (size_t)warp * D);
    const float4* __restrict__ P = (const float4*)(features + (size_t)p * D);
    const float4* __restrict__ N = (const float4*)(features + (size_t)n * D);
    float sap = 0.0f, san = 0.0f;

    if (D == 1024) {
        float4 a  = __ldcs(&A[lane]);          // anchor: streaming (read-once)
        float4 pp = P[lane];
        float4 nn = N[lane];
        #pragma unroll
        for (int k = 1; k <= 8; k++) {
            float4 a2, p2, n2;
            if (k < 8) {
                a2 = __ldcs(&A[lane + 32 * k]);
                p2 = P[lane + 32 * k];
                n2 = N[lane + 32 * k];
            }
            float d;
            d = a.x - pp.x + EPSV; sap = fmaf(d, d, sap);
            d = a.y - pp.y + EPSV; sap = fmaf(d, d, sap);
            d = a.z - pp.z + EPSV; sap = fmaf(d, d, sap);
            d = a.w - pp.w + EPSV; sap = fmaf(d, d, sap);
            d = a.x - nn.x + EPSV; san = fmaf(d, d, san);
            d = a.y - nn.y + EPSV; san = fmaf(d, d, san);
            d = a.z - nn.z + EPSV; san = fmaf(d, d, san);
            d = a.w - nn.w + EPSV; san = fmaf(d, d, san);
            a = a2; pp = p2; nn = n2;
        }
    } else {
        int nv = D >> 2;
        for (int k = lane; k < nv; k += 32) {
            float4 a = A[k], pp = P[k], nn = N[k];
            float d;
            d = a.x - pp.x + EPSV; sap = fmaf(d, d, sap);
            d = a.y - pp.y + EPSV; sap = fmaf(d, d, sap);
            d = a.z - pp.z + EPSV; sap = fmaf(d, d, sap);
            d = a.w - pp.w + EPSV; sap = fmaf(d, d, sap);
            d = a.x - nn.x + EPSV; san = fmaf(d, d, san);
            d = a.y - nn.y + EPSV; san = fmaf(d, d, san);
            d = a.z - nn.z + EPSV; san = fmaf(d, d, san);
            d = a.w - nn.w + EPSV; san = fmaf(d, d, san);
        }
    }
    #pragma unroll
    for (int off = 16; off > 0; off >>= 1) {
        sap += __shfl_down_sync(0xffffffffu, sap, off);
        san += __shfl_down_sync(0xffffffffu, san, off);
    }
    if (lane == 0)
        g_loss[warp] = fmaxf(sqrtf(sap) - sqrtf(san) + MARGIN, 0.0f);
}

// ================================================================ kernel C
// Deterministic single-block reduction (-1 = invalid anchor).
__global__ void k_reduce(float* __restrict__ out, int B) {
    __shared__ float s_sum[1024];
    __shared__ int   s_cnt[1024];
    int t = threadIdx.x;
    float sum = 0.0f;
    int cnt = 0;
    for (int i = t; i < B; i += blockDim.x) {
        float v = g_loss[i];
        if (v >= 0.0f) { sum += v; cnt++; }
    }
    s_sum[t] = sum;
    s_cnt[t] = cnt;
    __syncthreads();
    for (int off = (int)blockDim.x >> 1; off > 0; off >>= 1) {
        if (t < off) {
            s_sum[t] += s_sum[t + off];
            s_cnt[t] += s_cnt[t + off];
        }
        __syncthreads();
    }
    if (t == 0) {
        int c = s_cnt[0];
        out[0] = (c > 0) ? (s_sum[0] / (float)c) : 0.0f;
    }
}

// ================================================================ launch
extern "C" void kernel_launch(void* const* d_in, const int* in_sizes, int n_in,
                              void* d_out, int out_size) {
    int i_feat = (in_sizes[0] >= in_sizes[1]) ? 0 : 1;
    int i_lab  = 1 - i_feat;
    const float* features = (const float*)d_in[i_feat];
    const void*  labels   = d_in[i_lab];
    int B = in_sizes[i_lab];
    int D = in_sizes[i_feat] / B;

    void* occ_ptr = nullptr;
    cudaGetSymbolAddress(&occ_ptr, g_occ);                 // query only, no alloc
    cudaMemsetAsync(occ_ptr, 0xFF, sizeof(OccTab));        // init tab + diff to UINF

    k_occ   <<<(B + 255) / 256, 256>>>(labels, B);
    k_dist  <<<(B + 7) / 8, 256>>>(features, B, D);
    k_reduce<<<1, 1024>>>((float*)d_out, B);
}

// round 9
// speedup vs baseline: 1.1221x; 1.1221x over previous
#include <cuda_runtime.h>
#include <cstdint>

#define MARGIN 0.3f
#define EPSV   1e-6f

#define MAX_B 8192
#define MAX_L 1024
#define UINF  0xFFFFFFFFu

// Single memset-able init region (0xFF -> all UINF).
struct OccTab {
    unsigned int m1[MAX_L];   // first-occurrence index per label
    unsigned int m2[MAX_L];   // second-occurrence index per label
    unsigned int diff;        // first index with label != label[0]
};
__device__ OccTab g_occ;
__device__ int    g_lab32[MAX_B];   // decoded int32 labels
__device__ float  g_loss[MAX_B];    // per-anchor loss; -1.0f = invalid

// ================================================================ kernel A
// One pass, retry-free: two-min via atomicMin pair (loser-feeds-m2 trick).
__global__ void k_occ(const void* __restrict__ labels, int B) {
    int t = threadIdx.x;
    int gtid = blockIdx.x * blockDim.x + t;
    int lane = t & 31;
    __shared__ unsigned s_diff;
    if (t == 0) s_diff = UINF;

    // dtype detect, block-local + redundant (labels are tiny, L2-hot).
    // Odd 32-bit words < B are high halves of int64 labels (zero when
    // labels < 2^32) or independent int32 labels (never all zero).
    const int* w = (const int*)labels;
    int any = 0;
    for (int i = 2 * t + 1; i < B; i += 2 * blockDim.x) any |= w[i];
    int is64 = (__syncthreads_or(any) == 0);

    int l0 = is64 ? (int)((const long long*)labels)[0] : w[0];

    unsigned cand = UINF;
    if (gtid < B) {
        int lab = is64 ? (int)((const long long*)labels)[gtid] : w[gtid];
        g_lab32[gtid] = lab;

        if ((unsigned)lab < MAX_L) {
            unsigned idx = (unsigned)gtid;
            // Two-min in one pass: whoever loses the m1 comparison is a
            // candidate for m2. The final minimum never loses, so m2
            // converges to the second-smallest index for this label.
            unsigned old = atomicMin(&g_occ.m1[lab], idx);
            if (old != UINF)
                atomicMin(&g_occ.m2[lab], (idx < old) ? old : idx);
        }
        if (lab != l0) cand = (unsigned)gtid;
    }

    // diff: warp reduce -> smem -> one global atomic per block
    #pragma unroll
    for (int off = 16; off > 0; off >>= 1)
        cand = min(cand, __shfl_down_sync(0xffffffffu, cand, off));
    if (lane == 0 && cand != UINF) atomicMin(&s_diff, cand);
    __syncthreads();
    if (t == 0 && s_diff != UINF) atomicMin(&g_occ.diff, s_diff);
}

// ================================================================ kernel B
// Warp per anchor: resolve pos/neg from table, then distances.
__global__ void k_dist(const float* __restrict__ features, int B, int D) {
    int warp = (blockIdx.x * blockDim.x + threadIdx.x) >> 5;
    int lane = threadIdx.x & 31;
    if (warp >= B) return;

    int lab = g_lab32[warp];
    unsigned p = UINF, n = UINF;
    if ((unsigned)lab < MAX_L) {
        unsigned m1 = __ldcg(&g_occ.m1[lab]);
        p = (m1 == (unsigned)warp) ? __ldcg(&g_occ.m2[lab]) : m1;
        n = (lab != g_lab32[0]) ? 0u : __ldcg(&g_occ.diff);
    }
    if (p == UINF || n == UINF) {
        if (lane == 0) g_loss[warp] = -1.0f;
        return;
    }

    const float4* __restrict__ A = (const float4*)(features + (size_t)warp * D);
    const float4* __restrict__ P = (const float4*)(features + (size_t)p * D);
    const float4* __restrict__ N = (const float4*)(features + (size_t)n * D);
    float sap = 0.0f, san = 0.0f;

    if (D == 1024) {
        float4 a  = __ldcs(&A[lane]);          // anchor: streaming (read-once)
        float4 pp = P[lane];
        float4 nn = N[lane];
        #pragma unroll
        for (int k = 1; k <= 8; k++) {
            float4 a2, p2, n2;
            if (k < 8) {
                a2 = __ldcs(&A[lane + 32 * k]);
                p2 = P[lane + 32 * k];
                n2 = N[lane + 32 * k];
            }
            float d;
            d = a.x - pp.x + EPSV; sap = fmaf(d, d, sap);
            d = a.y - pp.y + EPSV; sap = fmaf(d, d, sap);
            d = a.z - pp.z + EPSV; sap = fmaf(d, d, sap);
            d = a.w - pp.w + EPSV; sap = fmaf(d, d, sap);
            d = a.x - nn.x + EPSV; san = fmaf(d, d, san);
            d = a.y - nn.y + EPSV; san = fmaf(d, d, san);
            d = a.z - nn.z + EPSV; san = fmaf(d, d, san);
            d = a.w - nn.w + EPSV; san = fmaf(d, d, san);
            a = a2; pp = p2; nn = n2;
        }
    } else {
        int nv = D >> 2;
        for (int k = lane; k < nv; k += 32) {
            float4 a = A[k], pp = P[k], nn = N[k];
            float d;
            d = a.x - pp.x + EPSV; sap = fmaf(d, d, sap);
            d = a.y - pp.y + EPSV; sap = fmaf(d, d, sap);
            d = a.z - pp.z + EPSV; sap = fmaf(d, d, sap);
            d = a.w - pp.w + EPSV; sap = fmaf(d, d, sap);
            d = a.x - nn.x + EPSV; san = fmaf(d, d, san);
            d = a.y - nn.y + EPSV; san = fmaf(d, d, san);
            d = a.z - nn.z + EPSV; san = fmaf(d, d, san);
            d = a.w - nn.w + EPSV; san = fmaf(d, d, san);
        }
    }
    #pragma unroll
    for (int off = 16; off > 0; off >>= 1) {
        sap += __shfl_down_sync(0xffffffffu, sap, off);
        san += __shfl_down_sync(0xffffffffu, san, off);
    }
    if (lane == 0)
        g_loss[warp] = fmaxf(sqrtf(sap) - sqrtf(san) + MARGIN, 0.0f);
}

// ================================================================ kernel C
// Deterministic single-block reduction (-1 = invalid anchor).
__global__ void k_reduce(float* __restrict__ out, int B) {
    __shared__ float s_sum[1024];
    __shared__ int   s_cnt[1024];
    int t = threadIdx.x;
    float sum = 0.0f;
    int cnt = 0;
    for (int i = t; i < B; i += blockDim.x) {
        float v = g_loss[i];
        if (v >= 0.0f) { sum += v; cnt++; }
    }
    s_sum[t] = sum;
    s_cnt[t] = cnt;
    __syncthreads();
    for (int off = (int)blockDim.x >> 1; off > 0; off >>= 1) {
        if (t < off) {
            s_sum[t] += s_sum[t + off];
            s_cnt[t] += s_cnt[t + off];
        }
        __syncthreads();
    }
    if (t == 0) {
        int c = s_cnt[0];
        out[0] = (c > 0) ? (s_sum[0] / (float)c) : 0.0f;
    }
}

// ================================================================ launch
extern "C" void kernel_launch(void* const* d_in, const int* in_sizes, int n_in,
                              void* d_out, int out_size) {
    int i_feat = (in_sizes[0] >= in_sizes[1]) ? 0 : 1;
    int i_lab  = 1 - i_feat;
    const float* features = (const float*)d_in[i_feat];
    const void*  labels   = d_in[i_lab];
    int B = in_sizes[i_lab];
    int D = in_sizes[i_feat] / B;

    void* occ_ptr = nullptr;
    cudaGetSymbolAddress(&occ_ptr, g_occ);              // address query, no alloc
    cudaMemsetAsync(occ_ptr, 0xFF, sizeof(OccTab));     // m1/m2/diff -> UINF

    k_occ   <<<(B + 127) / 128, 128>>>(labels, B);      // 64 blocks, chip-spread
    k_dist  <<<(B + 7) / 8, 256>>>(features, B, D);
    k_reduce<<<1, 1024>>>((float*)d_out, B);
}

// round 10
// speedup vs baseline: 1.3802x; 1.2300x over previous
#include <cuda_runtime.h>
#include <cstdint>

#define MARGIN 0.3f
#define EPSV   1e-6f

#define MAX_B 8192
#define MAX_L 1024
#define INF_I 0x7fffffff

__device__ int2   g_pair[MAX_B];    // per-anchor {pos_idx, neg_idx} (INF_I = none)
__device__ float2 g_part[MAX_B/16 + 1]; // per-block {loss_sum, valid_cnt}

__device__ __forceinline__ int read_label(const void* lab, int i, int is64) {
    if (is64) return (int)((const long long*)lab)[i];
    return ((const int*)lab)[i];
}

// ================================================================ kernel A
// One block. Smem label tables, SINGLE pass two-min (loser-feeds-m2 trick).
__global__ void k_labels(const void* __restrict__ labels, int B) {
    __shared__ int s_lab[MAX_B];    // cached decoded labels (32 KB)
    __shared__ int s_min1[MAX_L];
    __shared__ int s_min2[MAX_L];
    __shared__ int s_flag;          // nonzero odd word -> labels are int32
    __shared__ int s_diff;          // first index with label != labels[0]
    int t = threadIdx.x;
    int nt = blockDim.x;
    int lane = t & 31;

    for (int j = t; j < MAX_L; j += nt) { s_min1[j] = INF_I; s_min2[j] = INF_I; }
    if (t == 0) { s_flag = 0; s_diff = INF_I; }
    __syncthreads();

    // dtype detect: odd 32-bit words < B are high halves of int64 labels
    // (zero for labels < 2^32) or independent int32 labels (never all zero).
    {
        const int* w = (const int*)labels;
        int any = 0;
        for (int i = 2 * t + 1; i < B; i += 2 * nt) any |= w[i];
        if (__any_sync(0xffffffffu, any != 0) && lane == 0) atomicOr(&s_flag, 1);
    }
    __syncthreads();
    int is64 = (s_flag == 0);

    // decode labels into smem (single global pass)
    for (int i = t; i < B; i += nt) s_lab[i] = read_label(labels, i, is64);
    __syncthreads();
    int l0 = s_lab[0];

    // SINGLE pass: two-min via atomicMin pair. Whoever loses the m1
    // comparison is a candidate for m2; the true min never loses, so m2
    // converges to the second-smallest index per label. Also track diff
    // privately, one warp-reduced atomic at the end.
    {
        int cand = INF_I;
        for (int i = t; i < B; i += nt) {
            int li = s_lab[i];
            if ((unsigned)li < MAX_L) {
                int old = atomicMin(&s_min1[li], i);
                if (old != INF_I)
                    atomicMin(&s_min2[li], (i < old) ? old : i);
            }
            if (li != l0 && i < cand) cand = i;
        }
        #pragma unroll
        for (int off = 16; off > 0; off >>= 1)
            cand = min(cand, __shfl_down_sync(0xffffffffu, cand, off));
        if (lane == 0 && cand != INF_I) atomicMin(&s_diff, cand);
    }
    __syncthreads();

    // resolve per-anchor pos/neg
    int d0 = s_diff;
    for (int i = t; i < B; i += nt) {
        int li = s_lab[i];
        int p = ((unsigned)li < MAX_L) ? s_min1[li] : INF_I;
        if (p == i) p = s_min2[li];
        int n = (li != l0) ? 0 : d0;
        g_pair[i] = make_int2(p, n);
    }
}

// ================================================================ kernel B
// Warp per anchor, 2-stage pipeline, block-partial reduction (deterministic).
__global__ void k_dist(const float* __restrict__ features, int B, int D) {
    __shared__ float s_loss[16];
    __shared__ int   s_val[16];
    int wib  = threadIdx.x >> 5;                 // warp in block (0..15)
    int warp = blockIdx.x * (blockDim.x >> 5) + wib;
    int lane = threadIdx.x & 31;

    float my_loss = 0.0f;
    int   my_val  = 0;

    if (warp < B) {
        int2 pn = g_pair[warp];
        if (pn.x != INF_I && pn.y != INF_I) {
            const float4* __restrict__ A = (const float4*)(features + (size_t)warp * D);
            const float4* __restrict__ P = (const float4*)(features + (size_t)pn.x * D);
            const float4* __restrict__ N = (const float4*)(features + (size_t)pn.y * D);
            float sap = 0.0f, san = 0.0f;

            if (D == 1024) {
                float4 a  = __ldcs(&A[lane]);    // anchor: streaming (read-once)
                float4 pp = P[lane];
                float4 nn = N[lane];
                #pragma unroll
                for (int k = 1; k <= 8; k++) {
                    float4 a2, p2, n2;
                    if (k < 8) {
                        a2 = __ldcs(&A[lane + 32 * k]);
                        p2 = P[lane + 32 * k];
                        n2 = N[lane + 32 * k];
                    }
                    float d;
                    d = a.x - pp.x + EPSV; sap = fmaf(d, d, sap);
                    d = a.y - pp.y + EPSV; sap = fmaf(d, d, sap);
                    d = a.z - pp.z + EPSV; sap = fmaf(d, d, sap);
                    d = a.w - pp.w + EPSV; sap = fmaf(d, d, sap);
                    d = a.x - nn.x + EPSV; san = fmaf(d, d, san);
                    d = a.y - nn.y + EPSV; san = fmaf(d, d, san);
                    d = a.z - nn.z + EPSV; san = fmaf(d, d, san);
                    d = a.w - nn.w + EPSV; san = fmaf(d, d, san);
                    a = a2; pp = p2; nn = n2;
                }
            } else {
                int nv = D >> 2;
                for (int k = lane; k < nv; k += 32) {
                    float4 a = A[k], pp = P[k], nn = N[k];
                    float d;
                    d = a.x - pp.x + EPSV; sap = fmaf(d, d, sap);
                    d = a.y - pp.y + EPSV; sap = fmaf(d, d, sap);
                    d = a.z - pp.z + EPSV; sap = fmaf(d, d, sap);
                    d = a.w - pp.w + EPSV; sap = fmaf(d, d, sap);
                    d = a.x - nn.x + EPSV; san = fmaf(d, d, san);
                    d = a.y - nn.y + EPSV; san = fmaf(d, d, san);
                    d = a.z - nn.z + EPSV; san = fmaf(d, d, san);
                    d = a.w - nn.w + EPSV; san = fmaf(d, d, san);
                }
            }
            #pragma unroll
            for (int off = 16; off > 0; off >>= 1) {
                sap += __shfl_down_sync(0xffffffffu, sap, off);
                san += __shfl_down_sync(0xffffffffu, san, off);
            }
            my_loss = fmaxf(sqrtf(sap) - sqrtf(san) + MARGIN, 0.0f);
            my_val  = 1;
        }
    }

    // block-partial reduction (fixed order -> deterministic)
    if (lane == 0) { s_loss[wib] = my_loss; s_val[wib] = my_val; }
    __syncthreads();
    if (threadIdx.x == 0) {
        float sum = 0.0f; int cnt = 0;
        #pragma unroll
        for (int j = 0; j < 16; j++) { sum += s_loss[j]; cnt += s_val[j]; }
        g_part[blockIdx.x] = make_float2(sum, (float)cnt);
    }
}

// ================================================================ kernel C
// Deterministic single-block reduction over block partials.
__global__ void k_reduce(float* __restrict__ out, int npart) {
    __shared__ float s_sum[512];
    __shared__ float s_cnt[512];
    int t = threadIdx.x;
    float sum = 0.0f, cnt = 0.0f;
    for (int i = t; i < npart; i += blockDim.x) {
        float2 v = g_part[i];
        sum += v.x; cnt += v.y;
    }
    s_sum[t] = sum;
    s_cnt[t] = cnt;
    __syncthreads();
    for (int off = (int)blockDim.x >> 1; off > 0; off >>= 1) {
        if (t < off) {
            s_sum[t] += s_sum[t + off];
            s_cnt[t] += s_cnt[t + off];
        }
        __syncthreads();
    }
    if (t == 0)
        out[0] = (s_cnt[0] > 0.0f) ? (s_sum[0] / s_cnt[0]) : 0.0f;
}

// ================================================================ launch
extern "C" void kernel_launch(void* const* d_in, const int* in_sizes, int n_in,
                              void* d_out, int out_size) {
    int i_feat = (in_sizes[0] >= in_sizes[1]) ? 0 : 1;
    int i_lab  = 1 - i_feat;
    const float* features = (const float*)d_in[i_feat];
    const void*  labels   = d_in[i_lab];
    int B = in_sizes[i_lab];
    int D = in_sizes[i_feat] / B;

    int nblk = (B + 15) / 16;       // 16 warps (anchors) per 512-thread block
    k_labels<<<1, 1024>>>(labels, B);
    k_dist  <<<nblk, 512>>>(features, B, D);
    k_reduce<<<1, 512>>>((float*)d_out, nblk);
}

// round 11
// speedup vs baseline: 1.4845x; 1.0756x over previous
#include <cuda_runtime.h>
#include <cstdint>

#define MARGIN 0.3f
#define EPSV   1e-6f

#define MAX_B 8192
#define MAX_L 1024
#define UINF  0xFFFFFFFFu

// Single memset-able region (0xFF -> all UINF).
struct OccTab {
    unsigned m1[MAX_L];   // first-occurrence index per label
    unsigned m2[MAX_L];   // second-occurrence index per label
    unsigned diff;        // first index with label != label[0]
};
__device__ OccTab g_occ;
__device__ int    g_lab32[MAX_B];        // decoded int32 labels
__device__ float2 g_part[MAX_B/16 + 1];  // per-block {loss_sum, valid_cnt}

// two-min insert: whoever loses the m1 comparison feeds m2; the true min
// never loses, so m2 converges to the second-smallest inserted value.
__device__ __forceinline__ void twomin_insert_smem(unsigned* m1, unsigned* m2, unsigned v) {
    unsigned old = atomicMin(m1, v);
    if (old != UINF) atomicMin(m2, (v < old) ? old : v);
}
__device__ __forceinline__ void twomin_insert_glob(unsigned* m1, unsigned* m2, unsigned v) {
    unsigned old = atomicMin(m1, v);
    if (old != UINF) atomicMin(m2, (v < old) ? old : v);
}

// ================================================================ kernel A
// Partitioned occurrence pass: per-block smem two-min tables, global merge.
__global__ void k_occ_part(const void* __restrict__ labels, int B) {
    __shared__ unsigned s_m1[MAX_L];
    __shared__ unsigned s_m2[MAX_L];
    __shared__ unsigned s_diff;
    int t = threadIdx.x;
    int nt = blockDim.x;
    int lane = t & 31;

    for (int j = t; j < MAX_L; j += nt) { s_m1[j] = UINF; s_m2[j] = UINF; }
    if (t == 0) s_diff = UINF;

    // dtype detect (redundant per block; labels are tiny and L2-hot).
    // Odd 32-bit words < B are high halves of int64 labels (zero when
    // labels < 2^32) or independent int32 labels (never all zero).
    const int* w = (const int*)labels;
    int any = 0;
    for (int i = 2 * t + 1; i < B; i += 2 * nt) any |= w[i];
    int is64 = (__syncthreads_or(any) == 0);   // also orders smem init

    int l0 = is64 ? (int)((const long long*)labels)[0] : w[0];

    // this block's slice: [base, base + slice)
    int slice = (B + gridDim.x - 1) / gridDim.x;
    int base  = blockIdx.x * slice;
    int end   = min(base + slice, B);

    unsigned cand = UINF;
    for (int i = base + t; i < end; i += nt) {
        int lab = is64 ? (int)((const long long*)labels)[i] : w[i];
        g_lab32[i] = lab;
        if ((unsigned)lab < MAX_L)
            twomin_insert_smem(&s_m1[lab], &s_m2[lab], (unsigned)i);
        if (lab != l0 && (unsigned)i < cand) cand = (unsigned)i;
    }

    // diff: warp reduce -> one smem atomic per warp -> one global per block
    #pragma unroll
    for (int off = 16; off > 0; off >>= 1)
        cand = min(cand, __shfl_down_sync(0xffffffffu, cand, off));
    if (lane == 0 && cand != UINF) atomicMin(&s_diff, cand);
    __syncthreads();

    // merge live local entries into the global table (spread, one wave)
    for (int j = t; j < MAX_L; j += nt) {
        unsigned v1 = s_m1[j];
        if (v1 != UINF) {
            twomin_insert_glob(&g_occ.m1[j], &g_occ.m2[j], v1);
            unsigned v2 = s_m2[j];
            if (v2 != UINF) twomin_insert_glob(&g_occ.m1[j], &g_occ.m2[j], v2);
        }
    }
    if (t == 0 && s_diff != UINF) atomicMin(&g_occ.diff, s_diff);
}

// ================================================================ kernel B
// Warp per anchor: resolve pos/neg from global table, distances, block partials.
__global__ void k_dist(const float* __restrict__ features, int B, int D) {
    __shared__ float s_loss[16];
    __shared__ int   s_val[16];
    int wib  = threadIdx.x >> 5;
    int warp = blockIdx.x * (blockDim.x >> 5) + wib;
    int lane = threadIdx.x & 31;

    float my_loss = 0.0f;
    int   my_val  = 0;

    if (warp < B) {
        int lab = g_lab32[warp];
        unsigned p = UINF, n = UINF;
        if ((unsigned)lab < MAX_L) {
            unsigned m1 = __ldcg(&g_occ.m1[lab]);
            p = (m1 == (unsigned)warp) ? __ldcg(&g_occ.m2[lab]) : m1;
            n = (lab != g_lab32[0]) ? 0u : __ldcg(&g_occ.diff);
        }
        if (p != UINF && n != UINF) {
            const float4* __restrict__ A = (const float4*)(features + (size_t)warp * D);
            const float4* __restrict__ P = (const float4*)(features + (size_t)p * D);
            const float4* __restrict__ N = (const float4*)(features + (size_t)n * D);
            float sap = 0.0f, san = 0.0f;

            if (D == 1024) {
                float4 a  = __ldcs(&A[lane]);    // anchor: streaming (read-once)
                float4 pp = P[lane];
                float4 nn = N[lane];
                #pragma unroll
                for (int k = 1; k <= 8; k++) {
                    float4 a2, p2, n2;
                    if (k < 8) {
                        a2 = __ldcs(&A[lane + 32 * k]);
                        p2 = P[lane + 32 * k];
                        n2 = N[lane + 32 * k];
                    }
                    float d;
                    d = a.x - pp.x + EPSV; sap = fmaf(d, d, sap);
                    d = a.y - pp.y + EPSV; sap = fmaf(d, d, sap);
                    d = a.z - pp.z + EPSV; sap = fmaf(d, d, sap);
                    d = a.w - pp.w + EPSV; sap = fmaf(d, d, sap);
                    d = a.x - nn.x + EPSV; san = fmaf(d, d, san);
                    d = a.y - nn.y + EPSV; san = fmaf(d, d, san);
                    d = a.z - nn.z + EPSV; san = fmaf(d, d, san);
                    d = a.w - nn.w + EPSV; san = fmaf(d, d, san);
                    a = a2; pp = p2; nn = n2;
                }
            } else {
                int nv = D >> 2;
                for (int k = lane; k < nv; k += 32) {
                    float4 a = A[k], pp = P[k], nn = N[k];
                    float d;
                    d = a.x - pp.x + EPSV; sap = fmaf(d, d, sap);
                    d = a.y - pp.y + EPSV; sap = fmaf(d, d, sap);
                    d = a.z - pp.z + EPSV; sap = fmaf(d, d, sap);
                    d = a.w - pp.w + EPSV; sap = fmaf(d, d, sap);
                    d = a.x - nn.x + EPSV; san = fmaf(d, d, san);
                    d = a.y - nn.y + EPSV; san = fmaf(d, d, san);
                    d = a.z - nn.z + EPSV; san = fmaf(d, d, san);
                    d = a.w - nn.w + EPSV; san = fmaf(d, d, san);
                }
            }
            #pragma unroll
            for (int off = 16; off > 0; off >>= 1) {
                sap += __shfl_down_sync(0xffffffffu, sap, off);
                san += __shfl_down_sync(0xffffffffu, san, off);
            }
            my_loss = fmaxf(sqrtf(sap) - sqrtf(san) + MARGIN, 0.0f);
            my_val  = 1;
        }
    }

    // block-partial reduction (fixed order -> deterministic)
    if (lane == 0) { s_loss[wib] = my_loss; s_val[wib] = my_val; }
    __syncthreads();
    if (threadIdx.x == 0) {
        float sum = 0.0f; int cnt = 0;
        #pragma unroll
        for (int j = 0; j < 16; j++) { sum += s_loss[j]; cnt += s_val[j]; }
        g_part[blockIdx.x] = make_float2(sum, (float)cnt);
    }
}

// ================================================================ kernel C
// Deterministic single-block reduction over block partials.
__global__ void k_reduce(float* __restrict__ out, int npart) {
    __shared__ float s_sum[512];
    __shared__ float s_cnt[512];
    int t = threadIdx.x;
    float sum = 0.0f, cnt = 0.0f;
    for (int i = t; i < npart; i += blockDim.x) {
        float2 v = g_part[i];
        sum += v.x; cnt += v.y;
    }
    s_sum[t] = sum;
    s_cnt[t] = cnt;
    __syncthreads();
    for (int off = (int)blockDim.x >> 1; off > 0; off >>= 1) {
        if (t < off) {
            s_sum[t] += s_sum[t + off];
            s_cnt[t] += s_cnt[t + off];
        }
        __syncthreads();
    }
    if (t == 0)
        out[0] = (s_cnt[0] > 0.0f) ? (s_sum[0] / s_cnt[0]) : 0.0f;
}

// ================================================================ launch
extern "C" void kernel_launch(void* const* d_in, const int* in_sizes, int n_in,
                              void* d_out, int out_size) {
    int i_feat = (in_sizes[0] >= in_sizes[1]) ? 0 : 1;
    int i_lab  = 1 - i_feat;
    const float* features = (const float*)d_in[i_feat];
    const void*  labels   = d_in[i_lab];
    int B = in_sizes[i_lab];
    int D = in_sizes[i_feat] / B;

    void* occ_ptr = nullptr;
    cudaGetSymbolAddress(&occ_ptr, g_occ);              // address query, no alloc
    cudaMemsetAsync(occ_ptr, 0xFF, sizeof(OccTab));     // m1/m2/diff -> UINF

    int nocc = min(8, (B + 1023) / 1024);               // 8 SMs share atomic work
    int nblk = (B + 15) / 16;                           // 16 anchors per 512-thr block
    k_occ_part<<<nocc, 1024>>>(labels, B);
    k_dist    <<<nblk, 512>>>(features, B, D);
    k_reduce  <<<1, 512>>>((float*)d_out, nblk);
}